// round 15
// baseline (speedup 1.0000x reference)
#include <cuda_runtime.h>
#include <cuda_bf16.h>

#define T_STEPS 64
#define BATCH   256
#define NI      2048
#define NH      4096
#define NO      128
#define BN      (BATCH * NH)      // 1048576
#define BO      (BATCH * NO)      // 32768
#define RBLK    64                // persistent recurrence blocks (co-resident, <=148 SMs)

// ---------------- persistent device scratch (static: no runtime allocs) ----------------
__device__ float g_cur1[(size_t)T_STEPS * BN];   // 256 MiB: precomputed layer-1 currents
__device__ float g_mem1[BN];
__device__ float g_spk1[BN];
__device__ float g_mem2[BO];
__device__ float g_W2T[NH * NO];                 // W2 transposed: [k][o], 2 MiB
__device__ float g_cur2p[8 * BO];                // 8 chunk partials for layer 2 (1 MiB)
__device__ unsigned g_barCnt;
__device__ volatile unsigned g_barGen;

// ---------------- packed f32x2 helpers (per-lane IEEE rn rounding) ---------------------
__device__ __forceinline__ void ffma2(unsigned long long &d, unsigned long long a,
                                      unsigned long long b) {
    asm("fma.rn.f32x2 %0, %1, %2, %0;" : "+l"(d) : "l"(a), "l"(b));
}
__device__ __forceinline__ unsigned long long dup2(float x) {
    unsigned long long r;
    asm("mov.b64 %0, {%1, %1};" : "=l"(r) : "f"(x));
    return r;
}
__device__ __forceinline__ float2 unp(unsigned long long v) {
    float2 r;
    asm("mov.b64 {%0, %1}, %2;" : "=f"(r.x), "=f"(r.y) : "l"(v));
    return r;
}

// ---------------- init: zero recurrent state + transpose W2 + reset barrier ------------
__global__ void init_kernel(const float* __restrict__ W2) {
    int i = blockIdx.x * blockDim.x + threadIdx.x;
    if (i < BN) g_mem1[i] = 0.0f;
    if (i < BO) g_mem2[i] = 0.0f;
    if (i < NH * NO) {                 // i = k*128 + o  ->  W2[o*NH + k]
        int k = i >> 7, o = i & (NO - 1);
        g_W2T[i] = W2[(size_t)o * NH + k];
    }
    if (i == 0) { g_barCnt = 0; g_barGen = 0; }
}

// ---------------- GEMM1 (split-K=4, 512-chunks, serial combine via gmem RMW) -----------
// R11-exact (87% of FFMA2 bank-rt ceiling — do not touch).
__global__ void __launch_bounds__(256, 2) gemm1_kernel(const float* __restrict__ X,
                                                       const float* __restrict__ W1,
                                                       const float* __restrict__ b1) {
    __shared__ float As[8][128];   // [k][m]
    __shared__ float Bs[8][128];   // [k][n]
    const int tid = threadIdx.x;
    const int bm = blockIdx.y * 128;
    const int bn = blockIdx.x * 128;

    const int ldr = tid >> 1;            // 0..127
    const int ldc = (tid & 1) << 2;      // 0 or 4

    const float* Ap = X  + (size_t)(bm + ldr) * NI + ldc;
    const float* Bp = W1 + (size_t)(bn + ldr) * NI + ldc;

    const int tr = (tid >> 4) << 3;      // row base 0..120 step 8
    const int c0 = (tid & 15) << 2;      // col base (2nd group at +64)

    unsigned long long acc[8][4];

    float4 av = *(const float4*)Ap;
    float4 bv = *(const float4*)Bp;

#pragma unroll 1
    for (int p = 0; p < 4; p++) {
#pragma unroll
        for (int i = 0; i < 8; i++)
#pragma unroll
            for (int j = 0; j < 4; j++) acc[i][j] = 0ull;

#pragma unroll 1
        for (int k0 = p * 512; k0 < (p + 1) * 512; k0 += 8) {
            As[ldc + 0][ldr] = av.x;  As[ldc + 1][ldr] = av.y;
            As[ldc + 2][ldr] = av.z;  As[ldc + 3][ldr] = av.w;
            Bs[ldc + 0][ldr] = bv.x;  Bs[ldc + 1][ldr] = bv.y;
            Bs[ldc + 2][ldr] = bv.z;  Bs[ldc + 3][ldr] = bv.w;
            __syncthreads();
            if (k0 + 8 < NI) {
                av = *(const float4*)(Ap + k0 + 8);
                bv = *(const float4*)(Bp + k0 + 8);
            }
#pragma unroll
            for (int kk = 0; kk < 8; kk++) {
                float4 a0 = *(const float4*)&As[kk][tr];
                float4 a1 = *(const float4*)&As[kk][tr + 4];
                ulonglong2 w0 = *(const ulonglong2*)&Bs[kk][c0];
                ulonglong2 w1 = *(const ulonglong2*)&Bs[kk][c0 + 64];
                unsigned long long ad[8];
                ad[0] = dup2(a0.x); ad[1] = dup2(a0.y); ad[2] = dup2(a0.z); ad[3] = dup2(a0.w);
                ad[4] = dup2(a1.x); ad[5] = dup2(a1.y); ad[6] = dup2(a1.z); ad[7] = dup2(a1.w);
#pragma unroll
                for (int i = 0; i < 8; i++) {
                    ffma2(acc[i][0], ad[i], w0.x);
                    ffma2(acc[i][1], ad[i], w0.y);
                    ffma2(acc[i][2], ad[i], w1.x);
                    ffma2(acc[i][3], ad[i], w1.y);
                }
            }
            __syncthreads();
        }

#pragma unroll
        for (int i = 0; i < 8; i++) {
            float2 q0 = unp(acc[i][0]);
            float2 q1 = unp(acc[i][1]);
            float2 q2 = unp(acc[i][2]);
            float2 q3 = unp(acc[i][3]);
            float* Crow = g_cur1 + (size_t)(bm + tr + i) * NH + bn;
            float4 lo = make_float4(q0.x, q0.y, q1.x, q1.y);
            float4 hi = make_float4(q2.x, q2.y, q3.x, q3.y);
            if (p == 0) {
                *(float4*)(Crow + c0)      = lo;
                *(float4*)(Crow + c0 + 64) = hi;
            } else if (p < 3) {
                float4 t0 = *(const float4*)(Crow + c0);
                float4 t1 = *(const float4*)(Crow + c0 + 64);
                t0.x = __fadd_rn(t0.x, lo.x); t0.y = __fadd_rn(t0.y, lo.y);
                t0.z = __fadd_rn(t0.z, lo.z); t0.w = __fadd_rn(t0.w, lo.w);
                t1.x = __fadd_rn(t1.x, hi.x); t1.y = __fadd_rn(t1.y, hi.y);
                t1.z = __fadd_rn(t1.z, hi.z); t1.w = __fadd_rn(t1.w, hi.w);
                *(float4*)(Crow + c0)      = t0;
                *(float4*)(Crow + c0 + 64) = t1;
            } else {
                float4 bias0 = *(const float4*)(b1 + bn + c0);
                float4 bias1 = *(const float4*)(b1 + bn + c0 + 64);
                float4 t0 = *(const float4*)(Crow + c0);
                float4 t1 = *(const float4*)(Crow + c0 + 64);
                t0.x = __fadd_rn(__fadd_rn(t0.x, lo.x), bias0.x);
                t0.y = __fadd_rn(__fadd_rn(t0.y, lo.y), bias0.y);
                t0.z = __fadd_rn(__fadd_rn(t0.z, lo.z), bias0.z);
                t0.w = __fadd_rn(__fadd_rn(t0.w, lo.w), bias0.w);
                t1.x = __fadd_rn(__fadd_rn(t1.x, hi.x), bias1.x);
                t1.y = __fadd_rn(__fadd_rn(t1.y, hi.y), bias1.y);
                t1.z = __fadd_rn(__fadd_rn(t1.z, hi.z), bias1.z);
                t1.w = __fadd_rn(__fadd_rn(t1.w, hi.w), bias1.w);
                *(float4*)(Crow + c0)      = t0;
                *(float4*)(Crow + c0 + 64) = t1;
            }
        }
    }
}

// ---------------- patch (split4-512 serial, element (0,0) — unchanged anchor) ----------
__global__ void patch_kernel(const float* __restrict__ X, const float* __restrict__ W1,
                             const float* __restrict__ b1) {
    int t = threadIdx.x;                             // 64 threads
    const float* xr = X + (size_t)t * BATCH * NI;    // row (t, b=0)
    float tot = 0.0f;
#pragma unroll 1
    for (int s = 0; s < 4; s++) {
        float acc = 0.0f;
        for (int k = s * 512; k < (s + 1) * 512; k++)
            acc = __fmaf_rn(xr[k], W1[k], acc);
        tot = __fadd_rn(tot, acc);
    }
    g_cur1[(size_t)(t * BATCH) * NH] = __fadd_rn(tot, b1[0]);
}

// ---------------- grid barrier for RBLK co-resident blocks -----------------------------
__device__ __forceinline__ void gsync() {
    __syncthreads();
    if (threadIdx.x == 0) {
        unsigned gen = g_barGen;
        __threadfence();
        if (atomicAdd(&g_barCnt, 1) == RBLK - 1) {
            g_barCnt = 0;
            __threadfence();
            g_barGen = gen + 1;
        } else {
            while (g_barGen == gen) { __nanosleep(32); }
            __threadfence();
        }
    }
    __syncthreads();
}

// ---------------- layer-2 combine + LIF (verbatim arithmetic from R14) -----------------
__device__ __forceinline__ void do_update2(int t2, const float* __restrict__ b2,
                                           float* __restrict__ out, int v) {
    float4 tot = make_float4(0.0f, 0.0f, 0.0f, 0.0f);
#pragma unroll
    for (int s = 0; s < 8; s++) {
        float4 p = ((const float4*)(g_cur2p + (size_t)s * BO))[v];
        tot.x = __fadd_rn(tot.x, p.x);
        tot.y = __fadd_rn(tot.y, p.y);
        tot.z = __fadd_rn(tot.z, p.z);
        tot.w = __fadd_rn(tot.w, p.w);
    }
    float4 bb = ((const float4*)b2)[v & 31];
    float4 m4 = ((const float4*)g_mem2)[v];
    float4 s4;
    {
        float c = __fadd_rn(tot.x, bb.x);
        float r = (m4.x > 1.0f) ? 1.0f : 0.0f;
        m4.x = __fsub_rn(__fmaf_rn(0.8f, m4.x, c), r);
        s4.x = (m4.x > 1.0f) ? 1.0f : 0.0f;
    }
    {
        float c = __fadd_rn(tot.y, bb.y);
        float r = (m4.y > 1.0f) ? 1.0f : 0.0f;
        m4.y = __fsub_rn(__fmaf_rn(0.8f, m4.y, c), r);
        s4.y = (m4.y > 1.0f) ? 1.0f : 0.0f;
    }
    {
        float c = __fadd_rn(tot.z, bb.z);
        float r = (m4.z > 1.0f) ? 1.0f : 0.0f;
        m4.z = __fsub_rn(__fmaf_rn(0.8f, m4.z, c), r);
        s4.z = (m4.z > 1.0f) ? 1.0f : 0.0f;
    }
    {
        float c = __fadd_rn(tot.w, bb.w);
        float r = (m4.w > 1.0f) ? 1.0f : 0.0f;
        m4.w = __fsub_rn(__fmaf_rn(0.8f, m4.w, c), r);
        s4.w = (m4.w > 1.0f) ? 1.0f : 0.0f;
    }
    ((float4*)g_mem2)[v] = m4;
    ((float4*)(out + (size_t)T_STEPS * NH + T_STEPS + (size_t)t2 * BO))[v] = s4;
}

// ---------------- persistent recurrence: all 64 steps, 2 grid barriers per step --------
// Phase A: update1(t) across all blocks (+ update2(t-1) on blocks 56..63 — independent).
// Phase B: layer2 chunk partials (block -> (chunk s = bid&7, batch group bid>>3)).
__global__ void __launch_bounds__(1024) rec_kernel(const float* __restrict__ b2,
                                                   float* __restrict__ out) {
    __shared__ float sp_s[32][64];     // [b][k-sub]  8 KB
    __shared__ float wt_s[64][128];    // [k-sub][o] 32 KB
    const int tid = threadIdx.x;
    const int bid = blockIdx.x;
    const int s  = bid & 7;            // layer-2 chunk
    const int b0 = (bid >> 3) * 32;    // layer-2 batch group
    const int k0 = s * 512;
    const int wid = tid >> 5;
    const int lane = tid & 31;
    const int gid = bid * 1024 + tid;  // 0..65535

#pragma unroll 1
    for (int t = 0; t < T_STEPS; t++) {
        // ---- phase A: layer-1 LIF update (4 strided float4 per thread) ----
#pragma unroll
        for (int it = 0; it < 4; it++) {
            int v = gid + it * (RBLK * 1024);          // < BN/4
            float4 m4 = ((const float4*)g_mem1)[v];
            float4 c4 = __ldcs(&((const float4*)(g_cur1 + (size_t)t * BN))[v]);
            float4 s4;
            {
                float r = (m4.x > 1.0f) ? 1.0f : 0.0f;
                m4.x = __fsub_rn(__fmaf_rn(0.9f, m4.x, c4.x), r);
                s4.x = (m4.x > 1.0f) ? 1.0f : 0.0f;
            }
            {
                float r = (m4.y > 1.0f) ? 1.0f : 0.0f;
                m4.y = __fsub_rn(__fmaf_rn(0.9f, m4.y, c4.y), r);
                s4.y = (m4.y > 1.0f) ? 1.0f : 0.0f;
            }
            {
                float r = (m4.z > 1.0f) ? 1.0f : 0.0f;
                m4.z = __fsub_rn(__fmaf_rn(0.9f, m4.z, c4.z), r);
                s4.z = (m4.z > 1.0f) ? 1.0f : 0.0f;
            }
            {
                float r = (m4.w > 1.0f) ? 1.0f : 0.0f;
                m4.w = __fsub_rn(__fmaf_rn(0.9f, m4.w, c4.w), r);
                s4.w = (m4.w > 1.0f) ? 1.0f : 0.0f;
            }
            ((float4*)g_mem1)[v] = m4;
            ((float4*)g_spk1)[v] = s4;
            if (v < NH / 4) ((float4*)(out + (size_t)t * NH))[v] = s4;  // spk1 row 0
            if (v == 0) out[T_STEPS * NH + t] = m4.x;                   // mem1[0,0]
        }
        // fused update2(t-1) on blocks 56..63 (8192 float4 exactly)
        if (t > 0 && bid >= RBLK - 8)
            do_update2(t - 1, b2, out, (bid - (RBLK - 8)) * 1024 + tid);

        gsync();   // spk1 ready for layer2; cur2p(t-1) consumed before overwrite

        // ---- phase B: layer-2 chunk partials (verbatim R14 body) ----
        {
            unsigned long long acc0 = 0ull, acc1 = 0ull;
#pragma unroll 1
            for (int sub = 0; sub < 8; sub++) {
                __syncthreads();
                if (tid < 512) {
                    int bb = tid >> 4, kq = tid & 15;
                    *(float4*)&sp_s[bb][kq * 4] =
                        *(const float4*)&g_spk1[(size_t)(b0 + bb) * NH + k0 + sub * 64 + kq * 4];
                }
                {
                    int idx = tid;
#pragma unroll
                    for (int rep = 0; rep < 2; rep++, idx += 1024) {
                        int kk = idx >> 5, oq = idx & 31;
                        *(float4*)&wt_s[kk][oq * 4] =
                            *(const float4*)&g_W2T[(size_t)(k0 + sub * 64 + kk) * NO + oq * 4];
                    }
                }
                __syncthreads();
#pragma unroll
                for (int kk = 0; kk < 64; kk++) {
                    unsigned long long a = dup2(sp_s[wid][kk]);
                    ulonglong2 w = *(const ulonglong2*)&wt_s[kk][lane * 4];
                    ffma2(acc0, a, w.x);
                    ffma2(acc1, a, w.y);
                }
            }
            float2 q0 = unp(acc0), q1 = unp(acc1);
            float* dst = g_cur2p + (size_t)s * BO + (size_t)(b0 + wid) * NO + lane * 4;
            *(float4*)dst = make_float4(q0.x, q0.y, q1.x, q1.y);
        }

        gsync();   // cur2p(t) complete before phase A(t+1) consumes it
    }

    // tail: update2 for the final step
    if (blockIdx.x >= RBLK - 8)
        do_update2(T_STEPS - 1, b2, out, (blockIdx.x - (RBLK - 8)) * 1024 + threadIdx.x);
}

// ---------------- launch ----------------
extern "C" void kernel_launch(void* const* d_in, const int* in_sizes, int n_in,
                              void* d_out, int out_size) {
    const float* x  = (const float*)d_in[0];
    const float* W1 = (const float*)d_in[1];
    const float* b1 = (const float*)d_in[2];
    const float* W2 = (const float*)d_in[3];
    const float* b2 = (const float*)d_in[4];
    float* out = (float*)d_out;

    init_kernel<<<BN / 256, 256>>>(W2);
    gemm1_kernel<<<dim3(NH / 128, (T_STEPS * BATCH) / 128), 256>>>(x, W1, b1);
    patch_kernel<<<1, T_STEPS>>>(x, W1, b1);
    rec_kernel<<<RBLK, 1024>>>(b2, out);
}

// round 16
// speedup vs baseline: 1.1743x; 1.1743x over previous
#include <cuda_runtime.h>
#include <cuda_bf16.h>

#define T_STEPS 64
#define BATCH   256
#define NI      2048
#define NH      4096
#define NO      128
#define BN      (BATCH * NH)      // 1048576
#define BO      (BATCH * NO)      // 32768
#define RBLK    128               // persistent recurrence blocks (<=148 SMs, co-resident)

// ---------------- persistent device scratch (static: no runtime allocs) ----------------
__device__ float g_cur1[(size_t)T_STEPS * BN];   // 256 MiB: precomputed layer-1 currents
__device__ float g_mem1[BN];
__device__ float g_spk1[BN];
__device__ float g_mem2[BO];
__device__ float g_W2T[NH * NO];                 // W2 transposed: [k][o], 2 MiB
__device__ float g_cur2p[8 * BO];                // 8 chunk partials for layer 2 (1 MiB)
__device__ unsigned g_barCnt;
__device__ volatile unsigned g_barGen;

// ---------------- packed f32x2 helpers (per-lane IEEE rn rounding) ---------------------
__device__ __forceinline__ void ffma2(unsigned long long &d, unsigned long long a,
                                      unsigned long long b) {
    asm("fma.rn.f32x2 %0, %1, %2, %0;" : "+l"(d) : "l"(a), "l"(b));
}
__device__ __forceinline__ unsigned long long dup2(float x) {
    unsigned long long r;
    asm("mov.b64 %0, {%1, %1};" : "=l"(r) : "f"(x));
    return r;
}
__device__ __forceinline__ float2 unp(unsigned long long v) {
    float2 r;
    asm("mov.b64 {%0, %1}, %2;" : "=f"(r.x), "=f"(r.y) : "l"(v));
    return r;
}

// ---------------- init: zero recurrent state + transpose W2 + reset barrier ------------
__global__ void init_kernel(const float* __restrict__ W2) {
    int i = blockIdx.x * blockDim.x + threadIdx.x;
    if (i < BN) g_mem1[i] = 0.0f;
    if (i < BO) g_mem2[i] = 0.0f;
    if (i < NH * NO) {                 // i = k*128 + o  ->  W2[o*NH + k]
        int k = i >> 7, o = i & (NO - 1);
        g_W2T[i] = W2[(size_t)o * NH + k];
    }
    if (i == 0) { g_barCnt = 0; g_barGen = 0; }
}

// ---------------- GEMM1 (split-K=4, 512-chunks, serial combine via gmem RMW) -----------
// R11-exact (87% of FFMA2 bank-rt ceiling — do not touch).
__global__ void __launch_bounds__(256, 2) gemm1_kernel(const float* __restrict__ X,
                                                       const float* __restrict__ W1,
                                                       const float* __restrict__ b1) {
    __shared__ float As[8][128];   // [k][m]
    __shared__ float Bs[8][128];   // [k][n]
    const int tid = threadIdx.x;
    const int bm = blockIdx.y * 128;
    const int bn = blockIdx.x * 128;

    const int ldr = tid >> 1;            // 0..127
    const int ldc = (tid & 1) << 2;      // 0 or 4

    const float* Ap = X  + (size_t)(bm + ldr) * NI + ldc;
    const float* Bp = W1 + (size_t)(bn + ldr) * NI + ldc;

    const int tr = (tid >> 4) << 3;      // row base 0..120 step 8
    const int c0 = (tid & 15) << 2;      // col base (2nd group at +64)

    unsigned long long acc[8][4];

    float4 av = *(const float4*)Ap;
    float4 bv = *(const float4*)Bp;

#pragma unroll 1
    for (int p = 0; p < 4; p++) {
#pragma unroll
        for (int i = 0; i < 8; i++)
#pragma unroll
            for (int j = 0; j < 4; j++) acc[i][j] = 0ull;

#pragma unroll 1
        for (int k0 = p * 512; k0 < (p + 1) * 512; k0 += 8) {
            As[ldc + 0][ldr] = av.x;  As[ldc + 1][ldr] = av.y;
            As[ldc + 2][ldr] = av.z;  As[ldc + 3][ldr] = av.w;
            Bs[ldc + 0][ldr] = bv.x;  Bs[ldc + 1][ldr] = bv.y;
            Bs[ldc + 2][ldr] = bv.z;  Bs[ldc + 3][ldr] = bv.w;
            __syncthreads();
            if (k0 + 8 < NI) {
                av = *(const float4*)(Ap + k0 + 8);
                bv = *(const float4*)(Bp + k0 + 8);
            }
#pragma unroll
            for (int kk = 0; kk < 8; kk++) {
                float4 a0 = *(const float4*)&As[kk][tr];
                float4 a1 = *(const float4*)&As[kk][tr + 4];
                ulonglong2 w0 = *(const ulonglong2*)&Bs[kk][c0];
                ulonglong2 w1 = *(const ulonglong2*)&Bs[kk][c0 + 64];
                unsigned long long ad[8];
                ad[0] = dup2(a0.x); ad[1] = dup2(a0.y); ad[2] = dup2(a0.z); ad[3] = dup2(a0.w);
                ad[4] = dup2(a1.x); ad[5] = dup2(a1.y); ad[6] = dup2(a1.z); ad[7] = dup2(a1.w);
#pragma unroll
                for (int i = 0; i < 8; i++) {
                    ffma2(acc[i][0], ad[i], w0.x);
                    ffma2(acc[i][1], ad[i], w0.y);
                    ffma2(acc[i][2], ad[i], w1.x);
                    ffma2(acc[i][3], ad[i], w1.y);
                }
            }
            __syncthreads();
        }

#pragma unroll
        for (int i = 0; i < 8; i++) {
            float2 q0 = unp(acc[i][0]);
            float2 q1 = unp(acc[i][1]);
            float2 q2 = unp(acc[i][2]);
            float2 q3 = unp(acc[i][3]);
            float* Crow = g_cur1 + (size_t)(bm + tr + i) * NH + bn;
            float4 lo = make_float4(q0.x, q0.y, q1.x, q1.y);
            float4 hi = make_float4(q2.x, q2.y, q3.x, q3.y);
            if (p == 0) {
                *(float4*)(Crow + c0)      = lo;
                *(float4*)(Crow + c0 + 64) = hi;
            } else if (p < 3) {
                float4 t0 = *(const float4*)(Crow + c0);
                float4 t1 = *(const float4*)(Crow + c0 + 64);
                t0.x = __fadd_rn(t0.x, lo.x); t0.y = __fadd_rn(t0.y, lo.y);
                t0.z = __fadd_rn(t0.z, lo.z); t0.w = __fadd_rn(t0.w, lo.w);
                t1.x = __fadd_rn(t1.x, hi.x); t1.y = __fadd_rn(t1.y, hi.y);
                t1.z = __fadd_rn(t1.z, hi.z); t1.w = __fadd_rn(t1.w, hi.w);
                *(float4*)(Crow + c0)      = t0;
                *(float4*)(Crow + c0 + 64) = t1;
            } else {
                float4 bias0 = *(const float4*)(b1 + bn + c0);
                float4 bias1 = *(const float4*)(b1 + bn + c0 + 64);
                float4 t0 = *(const float4*)(Crow + c0);
                float4 t1 = *(const float4*)(Crow + c0 + 64);
                t0.x = __fadd_rn(__fadd_rn(t0.x, lo.x), bias0.x);
                t0.y = __fadd_rn(__fadd_rn(t0.y, lo.y), bias0.y);
                t0.z = __fadd_rn(__fadd_rn(t0.z, lo.z), bias0.z);
                t0.w = __fadd_rn(__fadd_rn(t0.w, lo.w), bias0.w);
                t1.x = __fadd_rn(__fadd_rn(t1.x, hi.x), bias1.x);
                t1.y = __fadd_rn(__fadd_rn(t1.y, hi.y), bias1.y);
                t1.z = __fadd_rn(__fadd_rn(t1.z, hi.z), bias1.z);
                t1.w = __fadd_rn(__fadd_rn(t1.w, hi.w), bias1.w);
                *(float4*)(Crow + c0)      = t0;
                *(float4*)(Crow + c0 + 64) = t1;
            }
        }
    }
}

// ---------------- patch (split4-512 serial, element (0,0) — unchanged anchor) ----------
__global__ void patch_kernel(const float* __restrict__ X, const float* __restrict__ W1,
                             const float* __restrict__ b1) {
    int t = threadIdx.x;                             // 64 threads
    const float* xr = X + (size_t)t * BATCH * NI;    // row (t, b=0)
    float tot = 0.0f;
#pragma unroll 1
    for (int s = 0; s < 4; s++) {
        float acc = 0.0f;
        for (int k = s * 512; k < (s + 1) * 512; k++)
            acc = __fmaf_rn(xr[k], W1[k], acc);
        tot = __fadd_rn(tot, acc);
    }
    g_cur1[(size_t)(t * BATCH) * NH] = __fadd_rn(tot, b1[0]);
}

// ---------------- grid barrier for RBLK co-resident blocks -----------------------------
__device__ __forceinline__ void gsync() {
    __syncthreads();
    if (threadIdx.x == 0) {
        unsigned gen = g_barGen;
        __threadfence();
        if (atomicAdd(&g_barCnt, 1) == RBLK - 1) {
            g_barCnt = 0;
            __threadfence();
            g_barGen = gen + 1;
        } else {
            while (g_barGen == gen) { __nanosleep(32); }
            __threadfence();
        }
    }
    __syncthreads();
}

// ---------------- layer-2 combine + LIF (verbatim arithmetic) --------------------------
__device__ __forceinline__ void do_update2(int t2, const float* __restrict__ b2,
                                           float* __restrict__ out, int v) {
    float4 tot = make_float4(0.0f, 0.0f, 0.0f, 0.0f);
#pragma unroll
    for (int s = 0; s < 8; s++) {
        float4 p = ((const float4*)(g_cur2p + (size_t)s * BO))[v];
        tot.x = __fadd_rn(tot.x, p.x);
        tot.y = __fadd_rn(tot.y, p.y);
        tot.z = __fadd_rn(tot.z, p.z);
        tot.w = __fadd_rn(tot.w, p.w);
    }
    float4 bb = ((const float4*)b2)[v & 31];
    float4 m4 = ((const float4*)g_mem2)[v];
    float4 s4;
    {
        float c = __fadd_rn(tot.x, bb.x);
        float r = (m4.x > 1.0f) ? 1.0f : 0.0f;
        m4.x = __fsub_rn(__fmaf_rn(0.8f, m4.x, c), r);
        s4.x = (m4.x > 1.0f) ? 1.0f : 0.0f;
    }
    {
        float c = __fadd_rn(tot.y, bb.y);
        float r = (m4.y > 1.0f) ? 1.0f : 0.0f;
        m4.y = __fsub_rn(__fmaf_rn(0.8f, m4.y, c), r);
        s4.y = (m4.y > 1.0f) ? 1.0f : 0.0f;
    }
    {
        float c = __fadd_rn(tot.z, bb.z);
        float r = (m4.z > 1.0f) ? 1.0f : 0.0f;
        m4.z = __fsub_rn(__fmaf_rn(0.8f, m4.z, c), r);
        s4.z = (m4.z > 1.0f) ? 1.0f : 0.0f;
    }
    {
        float c = __fadd_rn(tot.w, bb.w);
        float r = (m4.w > 1.0f) ? 1.0f : 0.0f;
        m4.w = __fsub_rn(__fmaf_rn(0.8f, m4.w, c), r);
        s4.w = (m4.w > 1.0f) ? 1.0f : 0.0f;
    }
    ((float4*)g_mem2)[v] = m4;
    ((float4*)(out + (size_t)T_STEPS * NH + T_STEPS + (size_t)t2 * BO))[v] = s4;
}

// ---------------- persistent recurrence: 128 blocks x 512 thr, 2 barriers/step ---------
// Phase A: update1(t) over all 128 blocks (+ update2(t-1) on blocks 120..127).
// Phase B: layer2 chunk partials; block = (chunk s = bid&7, bgroup g = bid>>3, 16 rows).
__global__ void __launch_bounds__(512) rec_kernel(const float* __restrict__ b2,
                                                  float* __restrict__ out) {
    __shared__ float sp_s[16][64];     // [b][k-sub]   4 KB
    __shared__ float wt_s[64][128];    // [k-sub][o]  32 KB
    const int tid = threadIdx.x;
    const int bid = blockIdx.x;
    const int s  = bid & 7;            // layer-2 chunk
    const int b0 = (bid >> 3) * 16;    // layer-2 batch group (16 rows)
    const int k0 = s * 512;
    const int row = tid >> 5;          // 0..15
    const int lane = tid & 31;         // o/4
    const int gid = bid * 512 + tid;   // 0..65535

#pragma unroll 1
    for (int t = 0; t < T_STEPS; t++) {
        // ---- phase A: layer-1 LIF update (4 strided float4 per thread) ----
#pragma unroll
        for (int it = 0; it < 4; it++) {
            int v = gid + it * (RBLK * 512);           // < BN/4
            float4 m4 = ((const float4*)g_mem1)[v];
            float4 c4 = __ldcs(&((const float4*)(g_cur1 + (size_t)t * BN))[v]);
            float4 s4;
            {
                float r = (m4.x > 1.0f) ? 1.0f : 0.0f;
                m4.x = __fsub_rn(__fmaf_rn(0.9f, m4.x, c4.x), r);
                s4.x = (m4.x > 1.0f) ? 1.0f : 0.0f;
            }
            {
                float r = (m4.y > 1.0f) ? 1.0f : 0.0f;
                m4.y = __fsub_rn(__fmaf_rn(0.9f, m4.y, c4.y), r);
                s4.y = (m4.y > 1.0f) ? 1.0f : 0.0f;
            }
            {
                float r = (m4.z > 1.0f) ? 1.0f : 0.0f;
                m4.z = __fsub_rn(__fmaf_rn(0.9f, m4.z, c4.z), r);
                s4.z = (m4.z > 1.0f) ? 1.0f : 0.0f;
            }
            {
                float r = (m4.w > 1.0f) ? 1.0f : 0.0f;
                m4.w = __fsub_rn(__fmaf_rn(0.9f, m4.w, c4.w), r);
                s4.w = (m4.w > 1.0f) ? 1.0f : 0.0f;
            }
            ((float4*)g_mem1)[v] = m4;
            ((float4*)g_spk1)[v] = s4;
            if (v < NH / 4) ((float4*)(out + (size_t)t * NH))[v] = s4;  // spk1 row 0
            if (v == 0) out[T_STEPS * NH + t] = m4.x;                   // mem1[0,0]
        }
        // fused update2(t-1) on blocks 120..127 (8 blocks x 512 thr x 2 = 8192 float4)
        if (t > 0 && bid >= RBLK - 8) {
            int base = (bid - (RBLK - 8)) * 1024 + tid;
            do_update2(t - 1, b2, out, base);
            do_update2(t - 1, b2, out, base + 512);
        }

        gsync();   // spk1 ready; cur2p(t-1) consumed before overwrite

        // ---- phase B: layer-2 chunk partials (per-element order verbatim R14) ----
        {
            unsigned long long acc0 = 0ull, acc1 = 0ull;
#pragma unroll 1
            for (int sub = 0; sub < 8; sub++) {
                __syncthreads();
                if (tid < 256) {
                    int bb = tid >> 4, kq = tid & 15;
                    *(float4*)&sp_s[bb][kq * 4] =
                        *(const float4*)&g_spk1[(size_t)(b0 + bb) * NH + k0 + sub * 64 + kq * 4];
                }
                {
                    int idx = tid;                  // 2048 float4 stores: 4 per thread
#pragma unroll
                    for (int rep = 0; rep < 4; rep++, idx += 512) {
                        int kk = idx >> 5, oq = idx & 31;
                        *(float4*)&wt_s[kk][oq * 4] =
                            *(const float4*)&g_W2T[(size_t)(k0 + sub * 64 + kk) * NO + oq * 4];
                    }
                }
                __syncthreads();
#pragma unroll
                for (int kk = 0; kk < 64; kk++) {
                    unsigned long long a = dup2(sp_s[row][kk]);
                    ulonglong2 w = *(const ulonglong2*)&wt_s[kk][lane * 4];
                    ffma2(acc0, a, w.x);
                    ffma2(acc1, a, w.y);
                }
            }
            float2 q0 = unp(acc0), q1 = unp(acc1);
            float* dst = g_cur2p + (size_t)s * BO + (size_t)(b0 + row) * NO + lane * 4;
            *(float4*)dst = make_float4(q0.x, q0.y, q1.x, q1.y);
        }

        gsync();   // cur2p(t) complete before phase A(t+1) consumes it
    }

    // tail: update2 for the final step
    if (blockIdx.x >= RBLK - 8) {
        int base = (blockIdx.x - (RBLK - 8)) * 1024 + threadIdx.x;
        do_update2(T_STEPS - 1, b2, out, base);
        do_update2(T_STEPS - 1, b2, out, base + 512);
    }
}

// ---------------- launch ----------------
extern "C" void kernel_launch(void* const* d_in, const int* in_sizes, int n_in,
                              void* d_out, int out_size) {
    const float* x  = (const float*)d_in[0];
    const float* W1 = (const float*)d_in[1];
    const float* b1 = (const float*)d_in[2];
    const float* W2 = (const float*)d_in[3];
    const float* b2 = (const float*)d_in[4];
    float* out = (float*)d_out;

    init_kernel<<<BN / 256, 256>>>(W2);
    gemm1_kernel<<<dim3(NH / 128, (T_STEPS * BATCH) / 128), 256>>>(x, W1, b1);
    patch_kernel<<<1, T_STEPS>>>(x, W1, b1);
    rec_kernel<<<RBLK, 512>>>(b2, out);
}